// round 1
// baseline (speedup 1.0000x reference)
#include <cuda_runtime.h>
#include <cuda_bf16.h>
#include <math.h>

// ---------------- problem constants ----------------
#define BATCH      32
#define T_SAMPLES  480000
#define FRAME_LEN  400
#define FRAME_SHIFT 160
#define NFFT       512
#define NK         257          // rfft bins
#define NMEL       80
#define NFRAMES    2998         // (480000-400)/160 + 1
#define M_TOTAL    (BATCH*NFRAMES)   // 95936
#define SCALE      32768.0f
#define PREEMPH    0.97f
#define EPS_F      1.1920928955078125e-07f

#define PSTRIDE    260          // padded power row stride (float4-aligned)

// ---------------- scratch (static device globals; no allocation) ----------------
__device__ float g_frames[(size_t)M_TOTAL * NFFT];     // ~196.5 MB windowed frames
__device__ float g_power [(size_t)M_TOTAL * PSTRIDE];  // ~99.8 MB power spectrum (cols 257..259 stay 0)
#define NCHUNK 12
__device__ float g_partial[BATCH * NCHUNK * NMEL];
__device__ float g_mean   [BATCH * NMEL];

// ================= kernel 1: framing + mean removal + preemph + window =================
// grid (NFRAMES, BATCH), block 128
__global__ void k_preprocess(const float* __restrict__ wav,
                             const float* __restrict__ window)
{
    __shared__ float sx[FRAME_LEN];
    __shared__ float red[4];
    const int f = blockIdx.x, b = blockIdx.y;
    const int tid = threadIdx.x;
    const float* x = wav + (size_t)b * T_SAMPLES + (size_t)f * FRAME_SHIFT;

    float s = 0.f;
    for (int i = tid; i < FRAME_LEN; i += 128) {
        float v = x[i] * SCALE;
        sx[i] = v;
        s += v;
    }
    // warp reduce
    #pragma unroll
    for (int off = 16; off > 0; off >>= 1)
        s += __shfl_xor_sync(0xffffffffu, s, off);
    if ((tid & 31) == 0) red[tid >> 5] = s;
    __syncthreads();
    const float c = (red[0] + red[1] + red[2] + red[3]) * (1.0f / FRAME_LEN);

    float* dst = g_frames + (size_t)(b * NFRAMES + f) * NFFT;
    for (int i = tid; i < NFFT; i += 128) {
        float v = 0.f;
        if (i < FRAME_LEN) {
            float zi = sx[i] - c;
            float zp = ((i == 0) ? sx[0] : sx[i - 1]) - c;
            v = (zi - PREEMPH * zp) * window[i];
        }
        dst[i] = v;
    }
}

// ================= kernel 2: DFT GEMM + power epilogue =================
// C tile: BM=128 frames x BN=32 bins (cos & sin simultaneously), BK=32
// 128 threads: 16 f-threads x 8 bin-threads; thread tile 8 frames x 4 bins x (r,i)
#define BM 128
#define BN 32
#define BK 32
__global__ __launch_bounds__(128)
void k_dft(const float* __restrict__ dcos, const float* __restrict__ dsin)
{
    __shared__ float As[BK][BM + 4];   // [t][frame], padded
    __shared__ float Cs[BK][BN];       // [t][bin]
    __shared__ float Ss[BK][BN];

    const int tid   = threadIdx.x;
    const int mBase = blockIdx.x * BM;
    const int kBase = blockIdx.y * BN;
    const int tf = tid >> 3;   // 0..15  -> frames tf*8..tf*8+7
    const int tb = tid & 7;    // 0..7   -> bins  tb*4..tb*4+3
    const int lr = tid >> 3;   // loader row (0..15)
    const int lc = tid & 7;    // loader float4 col (0..7)

    float aR[8][4], aI[8][4];
    #pragma unroll
    for (int i = 0; i < 8; i++)
        #pragma unroll
        for (int j = 0; j < 4; j++) { aR[i][j] = 0.f; aI[i][j] = 0.f; }

    for (int kt = 0; kt < NFFT; kt += BK) {
        // load A tile (transpose into [t][frame])
        #pragma unroll
        for (int p = 0; p < 8; p++) {
            int row = p * 16 + lr;
            int gm  = mBase + row;
            float4 v = make_float4(0.f, 0.f, 0.f, 0.f);
            if (gm < M_TOTAL)
                v = *(const float4*)(g_frames + (size_t)gm * NFFT + kt + lc * 4);
            As[lc * 4 + 0][row] = v.x;
            As[lc * 4 + 1][row] = v.y;
            As[lc * 4 + 2][row] = v.z;
            As[lc * 4 + 3][row] = v.w;
        }
        // load cos/sin tiles (transpose into [t][bin])
        #pragma unroll
        for (int p = 0; p < 2; p++) {
            int kr = p * 16 + lr;
            int gk = kBase + kr;
            float4 cv = make_float4(0.f, 0.f, 0.f, 0.f);
            float4 sv = make_float4(0.f, 0.f, 0.f, 0.f);
            if (gk < NK) {
                cv = *(const float4*)(dcos + (size_t)gk * NFFT + kt + lc * 4);
                sv = *(const float4*)(dsin + (size_t)gk * NFFT + kt + lc * 4);
            }
            Cs[lc * 4 + 0][kr] = cv.x; Cs[lc * 4 + 1][kr] = cv.y;
            Cs[lc * 4 + 2][kr] = cv.z; Cs[lc * 4 + 3][kr] = cv.w;
            Ss[lc * 4 + 0][kr] = sv.x; Ss[lc * 4 + 1][kr] = sv.y;
            Ss[lc * 4 + 2][kr] = sv.z; Ss[lc * 4 + 3][kr] = sv.w;
        }
        __syncthreads();

        #pragma unroll 4
        for (int t = 0; t < BK; t++) {
            float4 a0 = *(const float4*)&As[t][tf * 8];
            float4 a1 = *(const float4*)&As[t][tf * 8 + 4];
            float4 c4 = *(const float4*)&Cs[t][tb * 4];
            float4 s4 = *(const float4*)&Ss[t][tb * 4];
            float av[8] = {a0.x, a0.y, a0.z, a0.w, a1.x, a1.y, a1.z, a1.w};
            float cv[4] = {c4.x, c4.y, c4.z, c4.w};
            float sv[4] = {s4.x, s4.y, s4.z, s4.w};
            #pragma unroll
            for (int fi = 0; fi < 8; fi++)
                #pragma unroll
                for (int bi = 0; bi < 4; bi++) {
                    aR[fi][bi] += av[fi] * cv[bi];
                    aI[fi][bi] += av[fi] * sv[bi];
                }
        }
        __syncthreads();
    }

    // epilogue: power = r^2 + i^2
    #pragma unroll
    for (int fi = 0; fi < 8; fi++) {
        int gm = mBase + tf * 8 + fi;
        if (gm >= M_TOTAL) continue;
        #pragma unroll
        for (int bi = 0; bi < 4; bi++) {
            int gk = kBase + tb * 4 + bi;
            if (gk < NK)
                g_power[(size_t)gm * PSTRIDE + gk] =
                    aR[fi][bi] * aR[fi][bi] + aI[fi][bi] * aI[fi][bi];
        }
    }
}

// ================= kernel 3: mel GEMM + log =================
// C tile: 64 frames x 80 mels; 256 threads = 16 f-threads x 16 m-threads
// thread tile: 4 frames x 5 mels. K chunked by 32 (9 chunks over 257).
#define MBM 64
__global__ __launch_bounds__(256)
void k_mel(const float* __restrict__ melf, float* __restrict__ out)
{
    __shared__ float Ps[32][68];   // [k][frame], padded to float4 alignment
    __shared__ float Fs[32][NMEL]; // [k][mel]

    const int tid   = threadIdx.x;
    const int mBase = blockIdx.x * MBM;
    const int tf = tid >> 4;     // 0..15 -> frames tf*4..+3
    const int tm = tid & 15;     // 0..15 -> mels tm*5..+4

    float acc[4][5];
    #pragma unroll
    for (int i = 0; i < 4; i++)
        #pragma unroll
        for (int j = 0; j < 5; j++) acc[i][j] = 0.f;

    for (int kc = 0; kc < 288; kc += 32) {
        // load power tile: 64 frames x 32 k (transpose to [k][frame])
        #pragma unroll
        for (int p = 0; p < 2; p++) {
            int row = p * 32 + (tid >> 3);
            int t4  = tid & 7;
            int gk  = kc + t4 * 4;
            int gm  = mBase + row;
            float4 v = make_float4(0.f, 0.f, 0.f, 0.f);
            if (gk < NK)  // gk==256 reads cols 256..259; 257..259 are hard zeros
                v = *(const float4*)(g_power + (size_t)gm * PSTRIDE + gk);
            Ps[t4 * 4 + 0][row] = v.x;
            Ps[t4 * 4 + 1][row] = v.y;
            Ps[t4 * 4 + 2][row] = v.z;
            Ps[t4 * 4 + 3][row] = v.w;
        }
        // load mel filter tile
        for (int i = tid; i < 32 * NMEL; i += 256) {
            int kk = i / NMEL, m = i % NMEL;
            int gk = kc + kk;
            Fs[kk][m] = (gk < NK) ? melf[(size_t)gk * NMEL + m] : 0.f;
        }
        __syncthreads();

        #pragma unroll 4
        for (int kk = 0; kk < 32; kk++) {
            float4 a = *(const float4*)&Ps[kk][tf * 4];
            float av[4] = {a.x, a.y, a.z, a.w};
            float fv[5];
            #pragma unroll
            for (int j = 0; j < 5; j++) fv[j] = Fs[kk][tm * 5 + j];
            #pragma unroll
            for (int fi = 0; fi < 4; fi++)
                #pragma unroll
                for (int j = 0; j < 5; j++)
                    acc[fi][j] += av[fi] * fv[j];
        }
        __syncthreads();
    }

    #pragma unroll
    for (int fi = 0; fi < 4; fi++) {
        int gm = mBase + tf * 4 + fi;   // M_TOTAL divisible by 64, no guard needed
        #pragma unroll
        for (int j = 0; j < 5; j++) {
            float v = logf(fmaxf(acc[fi][j], EPS_F));
            out[(size_t)gm * NMEL + tm * 5 + j] = v;
        }
    }
}

// ================= kernel 4a: CMN partial sums (deterministic, no atomics) =================
// grid (NCHUNK, BATCH), block 160 = 80 mels x 2 frame-subsets
__global__ void k_cmn_partial(const float* __restrict__ out)
{
    __shared__ float sm[160];
    const int ch = blockIdx.x, b = blockIdx.y;
    const int tid = threadIdx.x;
    const int m = tid % NMEL, s = tid / NMEL;
    const int f0 = ch * 256;
    const int fend = min(f0 + 256, NFRAMES);
    float acc = 0.f;
    for (int f = f0 + s; f < fend; f += 2)
        acc += out[((size_t)b * NFRAMES + f) * NMEL + m];
    sm[tid] = acc;
    __syncthreads();
    if (tid < NMEL)
        g_partial[(b * NCHUNK + ch) * NMEL + m] = sm[tid] + sm[tid + NMEL];
}

// ================= kernel 4b: reduce partials to means =================
__global__ void k_cmn_mean()
{
    int i = blockIdx.x * blockDim.x + threadIdx.x;
    if (i >= BATCH * NMEL) return;
    int b = i / NMEL, m = i % NMEL;
    float s = 0.f;
    #pragma unroll
    for (int c = 0; c < NCHUNK; c++)
        s += g_partial[(b * NCHUNK + c) * NMEL + m];
    g_mean[i] = s * (1.0f / NFRAMES);
}

// ================= kernel 4c: subtract mean =================
__global__ void k_cmn_sub(float* __restrict__ out)
{
    size_t i = (size_t)blockIdx.x * blockDim.x + threadIdx.x;
    if (i >= (size_t)M_TOTAL * NMEL) return;
    int m = (int)(i % NMEL);
    int b = (int)(i / ((size_t)NFRAMES * NMEL));
    out[i] -= g_mean[b * NMEL + m];
}

// ================= launch =================
extern "C" void kernel_launch(void* const* d_in, const int* in_sizes, int n_in,
                              void* d_out, int out_size)
{
    const float* wav    = (const float*)d_in[0];
    const float* window = (const float*)d_in[1];
    const float* melf   = (const float*)d_in[2];
    const float* dcos   = (const float*)d_in[3];
    const float* dsin   = (const float*)d_in[4];
    float* out = (float*)d_out;

    k_preprocess<<<dim3(NFRAMES, BATCH), 128>>>(wav, window);
    k_dft<<<dim3((M_TOTAL + BM - 1) / BM, (NK + BN - 1) / BN), 128>>>(dcos, dsin);
    k_mel<<<dim3(M_TOTAL / MBM), 256>>>(melf, out);
    k_cmn_partial<<<dim3(NCHUNK, BATCH), 160>>>(out);
    k_cmn_mean<<<dim3((BATCH * NMEL + 255) / 256), 256>>>();
    {
        size_t n = (size_t)M_TOTAL * NMEL;
        k_cmn_sub<<<dim3((unsigned)((n + 255) / 256)), 256>>>(out);
    }
}

// round 2
// speedup vs baseline: 2.7351x; 2.7351x over previous
#include <cuda_runtime.h>
#include <cuda_bf16.h>
#include <math.h>

// ---------------- problem constants ----------------
#define BATCH      32
#define T_SAMPLES  480000
#define FRAME_LEN  400
#define FRAME_SHIFT 160
#define NFFT       512
#define NK         257
#define NMEL       80
#define NFRAMES    2998
#define M_TOTAL    (BATCH*NFRAMES)   // 95936
#define SCALE      32768.0f
#define PREEMPH    0.97f
#define EPS_F      1.1920928955078125e-07f

// ---------------- scratch ----------------
#define NCHUNK 47
__device__ float g_partial[BATCH * NCHUNK * NMEL];
__device__ float g_mean   [BATCH * NMEL];

// =====================================================================
// Fused kernel: preprocess + Stockham FFT-512 (4x radix-4 + radix-2)
//               + power spectrum + sparse mel + log
// One frame per 128-thread block. grid = (NFRAMES, BATCH)
// =====================================================================
__global__ __launch_bounds__(128)
void k_fused(const float* __restrict__ wav,
             const float* __restrict__ window,
             const float* __restrict__ melf,
             const float* __restrict__ dcos,
             const float* __restrict__ dsin,
             float* __restrict__ out)
{
    __shared__ float Ar[512], Ai[512], Br[512], Bi[512];
    __shared__ float twc[512], tws[512];
    __shared__ float red[4];

    const int tid = threadIdx.x;
    const int f = blockIdx.x, b = blockIdx.y;
    const int gm = b * NFRAMES + f;

    // --- twiddle tables: row 1 of dft_cos/dft_sin = cos/sin(2*pi*t/512) ---
    #pragma unroll
    for (int i = tid; i < 512; i += 128) {
        twc[i] = dcos[512 + i];
        tws[i] = dsin[512 + i];
    }

    // --- load raw frame, scale, block-reduce mean ---
    const float* x = wav + (size_t)b * T_SAMPLES + (size_t)f * FRAME_SHIFT;
    float s = 0.f;
    for (int i = tid; i < FRAME_LEN; i += 128) {
        float v = x[i] * SCALE;
        Ar[i] = v;
        s += v;
    }
    #pragma unroll
    for (int off = 16; off > 0; off >>= 1)
        s += __shfl_xor_sync(0xffffffffu, s, off);
    if ((tid & 31) == 0) red[tid >> 5] = s;
    __syncthreads();
    const float mean = (red[0] + red[1] + red[2] + red[3]) * (1.0f / FRAME_LEN);

    // --- preemph + window into B (FFT input); imag = 0 ---
    #pragma unroll
    for (int i = tid; i < 512; i += 128) {
        float v = 0.f;
        if (i < FRAME_LEN) {
            float zi = Ar[i] - mean;
            float zp = ((i == 0) ? Ar[0] : Ar[i - 1]) - mean;
            v = (zi - PREEMPH * zp) * window[i];
        }
        Br[i] = v;
        Bi[i] = 0.f;
    }
    __syncthreads();

    // --- Stockham FFT: 4 radix-4 stages (B->A->B->A->B), then radix-2 (B->A) ---
    float* xr = Br; float* xi = Bi;
    float* yr = Ar; float* yi = Ai;

    #pragma unroll
    for (int t = 0; t < 4; t++) {
        const int sh = 2 * t;
        const int st = 1 << sh;        // s = 1,4,16,64
        const int p  = tid >> sh;
        const int q  = tid & (st - 1);
        const int i0 = q + st * p;     // == tid

        float ar = xr[i0],       ai_ = xi[i0];
        float br = xr[i0 + 128], bi_ = xi[i0 + 128];
        float cr = xr[i0 + 256], ci_ = xi[i0 + 256];
        float dr = xr[i0 + 384], di_ = xi[i0 + 384];

        float apcr = ar + cr, apci = ai_ + ci_;
        float amcr = ar - cr, amci = ai_ - ci_;
        float bpdr = br + dr, bpdi = bi_ + di_;
        float bmdr = br - dr, bmdi = bi_ - di_;

        // DIF radix-4 with e^{-i} convention
        float t0r = apcr + bpdr, t0i = apci + bpdi;
        float t2r = apcr - bpdr, t2i = apci - bpdi;
        float t1r = amcr + bmdi, t1i = amci - bmdr;   // (a-c) - i(b-d)
        float t3r = amcr - bmdi, t3i = amci + bmdr;   // (a-c) + i(b-d)

        // twiddles w^p = e^{-i 2pi p / n}; table index step = s
        const int tw = p * st;
        float c1 = twc[tw],     s1 = tws[tw];
        float c2 = twc[2 * tw], s2 = tws[2 * tw];
        float c3 = twc[3 * tw], s3 = tws[3 * tw];

        const int o = q + 4 * st * p;
        yr[o]          = t0r;
        yi[o]          = t0i;
        yr[o + st]     = t1r * c1 + t1i * s1;
        yi[o + st]     = t1i * c1 - t1r * s1;
        yr[o + 2 * st] = t2r * c2 + t2i * s2;
        yi[o + 2 * st] = t2i * c2 - t2r * s2;
        yr[o + 3 * st] = t3r * c3 + t3i * s3;
        yi[o + 3 * st] = t3i * c3 - t3r * s3;
        __syncthreads();

        float* tr = xr; xr = yr; yr = tr;
        float* ti = xi; xi = yi; yi = ti;
    }

    // radix-2 final stage: n=2, s=256 (x = B after 4 swaps, y = A)
    #pragma unroll
    for (int r = 0; r < 2; r++) {
        int q = tid + 128 * r;
        float ar = xr[q],       ai_ = xi[q];
        float br = xr[q + 256], bi_ = xi[q + 256];
        yr[q]       = ar + br;
        yi[q]       = ai_ + bi_;
        yr[q + 256] = ar - br;
        yi[q + 256] = ai_ - bi_;
    }
    __syncthreads();

    // --- power spectrum into Br[0..256] (yr/yi == Ar/Ai now) ---
    #pragma unroll
    for (int k = tid; k < NK; k += 128) {
        float re = yr[k], im = yi[k];
        Br[k] = re * re + im * im;
    }
    __syncthreads();

    // --- sparse mel + log ---
    if (tid < NMEL) {
        const int m = tid;
        // conservative support bounds; exact weights come from the table
        const float mel_lo = 1127.0f * logf(1.0f + 20.0f / 700.0f);
        const float mel_hi = 1127.0f * logf(1.0f + 8000.0f / 700.0f);
        const float delta  = (mel_hi - mel_lo) * (1.0f / (NMEL + 1));
        float left  = mel_lo + m * delta;
        float right = left + 2.0f * delta;
        float fl = 700.0f * (expf(left  * (1.0f / 1127.0f)) - 1.0f);
        float fr = 700.0f * (expf(right * (1.0f / 1127.0f)) - 1.0f);
        int klo = max(0,   (int)floorf(fl * (1.0f / 31.25f)) - 1);
        int khi = min(256, (int)ceilf (fr * (1.0f / 31.25f)) + 1);

        float acc = 0.f;
        for (int k = klo; k <= khi; k++)
            acc += Br[k] * melf[(size_t)k * NMEL + m];

        out[(size_t)gm * NMEL + m] = logf(fmaxf(acc, EPS_F));
    }
}

// ================= CMN =================
__global__ void k_cmn_partial(const float* __restrict__ out)
{
    __shared__ float sm[160];
    const int ch = blockIdx.x, b = blockIdx.y;
    const int tid = threadIdx.x;
    const int m = tid % NMEL, s = tid / NMEL;
    const int f0 = ch * 64;
    const int fend = min(f0 + 64, NFRAMES);
    float acc = 0.f;
    for (int f = f0 + s; f < fend; f += 2)
        acc += out[((size_t)b * NFRAMES + f) * NMEL + m];
    sm[tid] = acc;
    __syncthreads();
    if (tid < NMEL)
        g_partial[(b * NCHUNK + ch) * NMEL + m] = sm[tid] + sm[tid + NMEL];
}

__global__ void k_cmn_mean()
{
    int i = blockIdx.x * blockDim.x + threadIdx.x;
    if (i >= BATCH * NMEL) return;
    int b = i / NMEL, m = i % NMEL;
    float s = 0.f;
    #pragma unroll
    for (int c = 0; c < NCHUNK; c++)
        s += g_partial[(b * NCHUNK + c) * NMEL + m];
    g_mean[i] = s * (1.0f / NFRAMES);
}

__global__ void k_cmn_sub(float* __restrict__ out)
{
    size_t i = (size_t)blockIdx.x * blockDim.x + threadIdx.x;
    if (i >= (size_t)M_TOTAL * NMEL) return;
    int m = (int)(i % NMEL);
    int b = (int)(i / ((size_t)NFRAMES * NMEL));
    out[i] -= g_mean[b * NMEL + m];
}

// ================= launch =================
extern "C" void kernel_launch(void* const* d_in, const int* in_sizes, int n_in,
                              void* d_out, int out_size)
{
    const float* wav    = (const float*)d_in[0];
    const float* window = (const float*)d_in[1];
    const float* melf   = (const float*)d_in[2];
    const float* dcos   = (const float*)d_in[3];
    const float* dsin   = (const float*)d_in[4];
    float* out = (float*)d_out;

    k_fused<<<dim3(NFRAMES, BATCH), 128>>>(wav, window, melf, dcos, dsin, out);
    k_cmn_partial<<<dim3(NCHUNK, BATCH), 160>>>(out);
    k_cmn_mean<<<dim3((BATCH * NMEL + 255) / 256), 256>>>();
    {
        size_t n = (size_t)M_TOTAL * NMEL;
        k_cmn_sub<<<dim3((unsigned)((n + 255) / 256)), 256>>>(out);
    }
}

// round 3
// speedup vs baseline: 3.9961x; 1.4610x over previous
#include <cuda_runtime.h>
#include <cuda_bf16.h>
#include <math.h>

// ---------------- problem constants ----------------
#define BATCH      32
#define T_SAMPLES  480000
#define FRAME_LEN  400
#define FRAME_SHIFT 160
#define NFFT       512
#define NK         257
#define NMEL       80
#define NFRAMES    2998
#define NPAIRS     (NFRAMES/2)       // 1499
#define M_TOTAL    (BATCH*NFRAMES)   // 95936
#define SCALE      32768.0f
#define PREEMPH    0.97f
#define EPS_F      1.1920928955078125e-07f

// ---------------- scratch ----------------
#define NCHUNK 25
__device__ float g_partial[BATCH * NCHUNK * NMEL];
__device__ float g_mean   [BATCH * NMEL];

// =====================================================================
// Fused kernel: two frames packed into ONE complex FFT (real-packing).
// preprocess + Stockham FFT-512 (4x radix-4 + radix-2) + conjugate-
// symmetry split + power + sparse mel + log.
// One frame-PAIR per 128-thread block. grid = (NPAIRS, BATCH)
// =====================================================================
__global__ __launch_bounds__(128)
void k_fused(const float* __restrict__ wav,
             const float* __restrict__ window,
             const float* __restrict__ melf,
             const float* __restrict__ dcos,
             const float* __restrict__ dsin,
             float* __restrict__ out)
{
    __shared__ float Ar[512], Ai[512], Br[512], Bi[512];
    __shared__ float twc[512], tws[512];
    __shared__ float red0[4], red1[4];

    const int tid = threadIdx.x;
    const int p_  = blockIdx.x, b = blockIdx.y;
    const int f0  = 2 * p_;               // first frame of pair
    const int gm0 = b * NFRAMES + f0;

    // --- twiddle tables: row 1 of dft_cos/dft_sin = cos/sin(2*pi*t/512) ---
    #pragma unroll
    for (int i = tid; i < 512; i += 128) {
        twc[i] = dcos[512 + i];
        tws[i] = dsin[512 + i];
    }

    // --- load both frames (scaled) into Ar (frame0) / Ai (frame1), reduce means ---
    const float* x0 = wav + (size_t)b * T_SAMPLES + (size_t)f0 * FRAME_SHIFT;
    const float* x1 = x0 + FRAME_SHIFT;
    float s0 = 0.f, s1 = 0.f;
    for (int i = tid; i < FRAME_LEN; i += 128) {
        float v0 = x0[i] * SCALE;
        float v1 = x1[i] * SCALE;
        Ar[i] = v0; Ai[i] = v1;
        s0 += v0;   s1 += v1;
    }
    #pragma unroll
    for (int off = 16; off > 0; off >>= 1) {
        s0 += __shfl_xor_sync(0xffffffffu, s0, off);
        s1 += __shfl_xor_sync(0xffffffffu, s1, off);
    }
    if ((tid & 31) == 0) { red0[tid >> 5] = s0; red1[tid >> 5] = s1; }
    __syncthreads();
    const float mean0 = (red0[0] + red0[1] + red0[2] + red0[3]) * (1.0f / FRAME_LEN);
    const float mean1 = (red1[0] + red1[1] + red1[2] + red1[3]) * (1.0f / FRAME_LEN);

    // --- preemph + window; pack: Br = frame0 (real), Bi = frame1 (imag) ---
    #pragma unroll
    for (int i = tid; i < 512; i += 128) {
        float v0 = 0.f, v1 = 0.f;
        if (i < FRAME_LEN) {
            float w = window[i];
            float z0 = Ar[i] - mean0;
            float q0 = ((i == 0) ? Ar[0] : Ar[i - 1]) - mean0;
            v0 = (z0 - PREEMPH * q0) * w;
            float z1 = Ai[i] - mean1;
            float q1 = ((i == 0) ? Ai[0] : Ai[i - 1]) - mean1;
            v1 = (z1 - PREEMPH * q1) * w;
        }
        Br[i] = v0;
        Bi[i] = v1;
    }
    __syncthreads();

    // --- Stockham FFT: 4 radix-4 stages, then radix-2 ---
    float* xr = Br; float* xi = Bi;
    float* yr = Ar; float* yi = Ai;

    #pragma unroll
    for (int t = 0; t < 4; t++) {
        const int sh = 2 * t;
        const int st = 1 << sh;        // 1,4,16,64
        const int p  = tid >> sh;
        const int q  = tid & (st - 1);
        const int i0 = q + st * p;     // == tid

        float ar = xr[i0],       ai_ = xi[i0];
        float br = xr[i0 + 128], bi_ = xi[i0 + 128];
        float cr = xr[i0 + 256], ci_ = xi[i0 + 256];
        float dr = xr[i0 + 384], di_ = xi[i0 + 384];

        float apcr = ar + cr, apci = ai_ + ci_;
        float amcr = ar - cr, amci = ai_ - ci_;
        float bpdr = br + dr, bpdi = bi_ + di_;
        float bmdr = br - dr, bmdi = bi_ - di_;

        float t0r = apcr + bpdr, t0i = apci + bpdi;
        float t2r = apcr - bpdr, t2i = apci - bpdi;
        float t1r = amcr + bmdi, t1i = amci - bmdr;
        float t3r = amcr - bmdi, t3i = amci + bmdr;

        const int tw = p * st;
        float c1 = twc[tw],     s1_ = tws[tw];
        float c2 = twc[2 * tw], s2_ = tws[2 * tw];
        float c3 = twc[3 * tw], s3_ = tws[3 * tw];

        const int o = q + 4 * st * p;
        yr[o]          = t0r;
        yi[o]          = t0i;
        yr[o + st]     = t1r * c1 + t1i * s1_;
        yi[o + st]     = t1i * c1 - t1r * s1_;
        yr[o + 2 * st] = t2r * c2 + t2i * s2_;
        yi[o + 2 * st] = t2i * c2 - t2r * s2_;
        yr[o + 3 * st] = t3r * c3 + t3i * s3_;
        yi[o + 3 * st] = t3i * c3 - t3r * s3_;
        __syncthreads();

        float* tr = xr; xr = yr; yr = tr;
        float* ti = xi; xi = yi; yi = ti;
    }

    // radix-2 final stage (x=B, y=A)
    #pragma unroll
    for (int r = 0; r < 2; r++) {
        int q = tid + 128 * r;
        float ar = xr[q],       ai_ = xi[q];
        float br = xr[q + 256], bi_ = xi[q + 256];
        yr[q]       = ar + br;
        yi[q]       = ai_ + bi_;
        yr[q + 256] = ar - br;
        yi[q + 256] = ai_ - bi_;
    }
    __syncthreads();

    // --- conjugate-symmetry split + power. Result in Ar/Ai; Br/Bi free. ---
    // P0 -> Br[0..256], P1 -> Bi[0..256]
    for (int k = tid; k < NK; k += 128) {
        int n = (NFFT - k) & (NFFT - 1);
        float a = Ar[k], bb = Ai[k];
        float c = Ar[n], d  = Ai[n];
        float Xr = 0.5f * (a + c), Xi = 0.5f * (bb - d);
        float Yr = 0.5f * (bb + d), Yi = 0.5f * (c - a);
        Br[k] = Xr * Xr + Xi * Xi;
        Bi[k] = Yr * Yr + Yi * Yi;
    }
    __syncthreads();

    // --- sparse mel + log for both frames (160 outputs, 128 threads) ---
    for (int idx = tid; idx < 2 * NMEL; idx += 128) {
        const int fr = (idx < NMEL) ? 0 : 1;
        const int m  = idx - fr * NMEL;
        const float* P = fr ? Bi : Br;

        const float mel_lo = 1127.0f * logf(1.0f + 20.0f / 700.0f);
        const float mel_hi = 1127.0f * logf(1.0f + 8000.0f / 700.0f);
        const float delta  = (mel_hi - mel_lo) * (1.0f / (NMEL + 1));
        float left  = mel_lo + m * delta;
        float right = left + 2.0f * delta;
        float fl = 700.0f * (expf(left  * (1.0f / 1127.0f)) - 1.0f);
        float fr_ = 700.0f * (expf(right * (1.0f / 1127.0f)) - 1.0f);
        int klo = max(0,   (int)floorf(fl  * (1.0f / 31.25f)) - 1);
        int khi = min(256, (int)ceilf (fr_ * (1.0f / 31.25f)) + 1);

        float acc = 0.f;
        for (int k = klo; k <= khi; k++)
            acc += P[k] * melf[(size_t)k * NMEL + m];

        out[(size_t)(gm0 + fr) * NMEL + m] = logf(fmaxf(acc, EPS_F));
    }
}

// ================= CMN (vectorized) =================
// partial sums: grid (NCHUNK, BATCH), block 320 = 20 float4-lanes x 16 subsets
__global__ __launch_bounds__(320)
void k_cmn_partial(const float* __restrict__ out)
{
    __shared__ float4 sm[320];
    const int ch = blockIdx.x, b = blockIdx.y;
    const int tid = threadIdx.x;
    const int lane = tid % 20;      // float4 column
    const int s    = tid / 20;      // 0..15
    const int f0   = ch * 120;
    const int fend = min(f0 + 120, NFRAMES);

    float4 acc = make_float4(0.f, 0.f, 0.f, 0.f);
    for (int f = f0 + s; f < fend; f += 16) {
        float4 v = *(const float4*)(out + ((size_t)b * NFRAMES + f) * NMEL + lane * 4);
        acc.x += v.x; acc.y += v.y; acc.z += v.z; acc.w += v.w;
    }
    sm[tid] = acc;
    __syncthreads();
    #pragma unroll
    for (int h = 8; h > 0; h >>= 1) {
        if (s < h) {
            float4 o_ = sm[tid + 20 * h];
            float4 m_ = sm[tid];
            m_.x += o_.x; m_.y += o_.y; m_.z += o_.z; m_.w += o_.w;
            sm[tid] = m_;
        }
        __syncthreads();
    }
    if (s == 0)
        *(float4*)(g_partial + ((size_t)b * NCHUNK + ch) * NMEL + lane * 4) = sm[lane];
}

__global__ void k_cmn_mean()
{
    int i = blockIdx.x * blockDim.x + threadIdx.x;
    if (i >= BATCH * NMEL) return;
    int b = i / NMEL, m = i % NMEL;
    float s = 0.f;
    #pragma unroll
    for (int c = 0; c < NCHUNK; c++)
        s += g_partial[(b * NCHUNK + c) * NMEL + m];
    g_mean[i] = s * (1.0f / NFRAMES);
}

// subtract: float4 over the whole output
__global__ void k_cmn_sub(float* __restrict__ out)
{
    size_t i = (size_t)blockIdx.x * blockDim.x + threadIdx.x;
    const size_t n4 = (size_t)M_TOTAL * (NMEL / 4);
    if (i >= n4) return;
    int m4 = (int)(i % (NMEL / 4));
    int b  = (int)(i / ((size_t)NFRAMES * (NMEL / 4)));
    float4 mu = *(const float4*)(g_mean + b * NMEL + m4 * 4);
    float4 v  = *(float4*)(out + i * 4);
    v.x -= mu.x; v.y -= mu.y; v.z -= mu.z; v.w -= mu.w;
    *(float4*)(out + i * 4) = v;
}

// ================= launch =================
extern "C" void kernel_launch(void* const* d_in, const int* in_sizes, int n_in,
                              void* d_out, int out_size)
{
    const float* wav    = (const float*)d_in[0];
    const float* window = (const float*)d_in[1];
    const float* melf   = (const float*)d_in[2];
    const float* dcos   = (const float*)d_in[3];
    const float* dsin   = (const float*)d_in[4];
    float* out = (float*)d_out;

    k_fused<<<dim3(NPAIRS, BATCH), 128>>>(wav, window, melf, dcos, dsin, out);
    k_cmn_partial<<<dim3(NCHUNK, BATCH), 320>>>(out);
    k_cmn_mean<<<dim3((BATCH * NMEL + 255) / 256), 256>>>();
    {
        size_t n4 = (size_t)M_TOTAL * (NMEL / 4);
        k_cmn_sub<<<dim3((unsigned)((n4 + 255) / 256)), 256>>>(out);
    }
}

// round 4
// speedup vs baseline: 7.4225x; 1.8575x over previous
#include <cuda_runtime.h>
#include <cuda_bf16.h>
#include <math.h>

// ---------------- problem constants ----------------
#define BATCH      32
#define T_SAMPLES  480000
#define FRAME_LEN  400
#define FRAME_SHIFT 160
#define NFFT       512
#define NK         257
#define NMEL       80
#define NFRAMES    2998
#define NPAIRS     (NFRAMES/2)       // 1499
#define M_TOTAL    (BATCH*NFRAMES)   // 95936
#define SCALE      32768.0f
#define PREEMPH    0.97f
#define EPS_F      1.1920928955078125e-07f

// ---------------- scratch ----------------
#define NCHUNK 25
__device__ float g_partial[BATCH * NCHUNK * NMEL];
__device__ float g_mean   [BATCH * NMEL];

// 8-point DFT, e^{-i} convention, in place on register arrays
__device__ __forceinline__ void fft8(float* r, float* q)
{
    float t0r=r[0]+r[4], t0i=q[0]+q[4];
    float t1r=r[0]-r[4], t1i=q[0]-q[4];
    float t2r=r[2]+r[6], t2i=q[2]+q[6];
    float t3r=r[2]-r[6], t3i=q[2]-q[6];
    float e0r=t0r+t2r, e0i=t0i+t2i;
    float e2r=t0r-t2r, e2i=t0i-t2i;
    float e1r=t1r+t3i, e1i=t1i-t3r;
    float e3r=t1r-t3i, e3i=t1i+t3r;

    float s0r=r[1]+r[5], s0i=q[1]+q[5];
    float s1r=r[1]-r[5], s1i=q[1]-q[5];
    float s2r=r[3]+r[7], s2i=q[3]+q[7];
    float s3r=r[3]-r[7], s3i=q[3]-q[7];
    float o0r=s0r+s2r, o0i=s0i+s2i;
    float o2r=s0r-s2r, o2i=s0i-s2i;
    float o1r=s1r+s3i, o1i=s1i-s3r;
    float o3r=s1r-s3i, o3i=s1i+s3r;

    const float C = 0.70710678118654752440f;
    float u1r=(o1r+o1i)*C, u1i=(o1i-o1r)*C;
    float u2r=o2i,         u2i=-o2r;
    float u3r=(o3i-o3r)*C, u3i=-(o3r+o3i)*C;

    r[0]=e0r+o0r; q[0]=e0i+o0i;
    r[4]=e0r-o0r; q[4]=e0i-o0i;
    r[1]=e1r+u1r; q[1]=e1i+u1i;
    r[5]=e1r-u1r; q[5]=e1i-u1i;
    r[2]=e2r+u2r; q[2]=e2i+u2i;
    r[6]=e2r-u2r; q[6]=e2i-u2i;
    r[3]=e3r+u3r; q[3]=e3i+u3i;
    r[7]=e3r-u3r; q[7]=e3i-u3i;
}

// =====================================================================
// Fused kernel: 2 frame-pairs per 128-thread block (64 threads/FFT).
// preprocess -> radix-8^3 FFT (regs, 2 smem exchanges) -> conj split
// -> power -> sparse mel -> log
// =====================================================================
__global__ __launch_bounds__(128)
void k_fused(const float* __restrict__ wav,
             const float* __restrict__ window,
             const float* __restrict__ melf,
             const float* __restrict__ dcos,
             const float* __restrict__ dsin,
             float* __restrict__ out)
{
    __shared__ float twc[512], tws[512];
    __shared__ float sbR[2][576], sbI[2][576];
    __shared__ float red[2][2][2];   // [fid][warpInFft][frame]

    const int tid = threadIdx.x;
    const int fid = tid >> 6;        // which FFT in block
    const int lt  = tid & 63;        // lane within FFT (= u)
    const int b   = blockIdx.y;

    const int pa = 2 * blockIdx.x + fid;                // pair index
    const bool valid = (pa < NPAIRS);
    const int pc = valid ? pa : (NPAIRS - 1);
    const int f0 = 2 * pc;
    const int gm0 = b * NFRAMES + f0;

    float* bR = sbR[fid];
    float* bI = sbI[fid];

    // twiddle tables (row 1 of dft tables = cos/sin(2*pi*t/512))
    for (int i = tid; i < 512; i += 128) {
        twc[i] = dcos[512 + i];
        tws[i] = dsin[512 + i];
    }

    // ---- load raw frames + per-frame sums ----
    const float* x0 = wav + (size_t)b * T_SAMPLES + (size_t)f0 * FRAME_SHIFT;
    const float* x1 = x0 + FRAME_SHIFT;
    float s0 = 0.f, s1 = 0.f;
    for (int i = lt; i < FRAME_LEN; i += 64) {
        float v0 = x0[i] * SCALE;
        float v1 = x1[i] * SCALE;
        bR[i] = v0; bI[i] = v1;
        s0 += v0;   s1 += v1;
    }
    #pragma unroll
    for (int off = 16; off > 0; off >>= 1) {
        s0 += __shfl_xor_sync(0xffffffffu, s0, off);
        s1 += __shfl_xor_sync(0xffffffffu, s1, off);
    }
    if ((tid & 31) == 0) {
        int w = (tid >> 5) & 1;
        red[fid][w][0] = s0;
        red[fid][w][1] = s1;
    }
    __syncthreads();   // also covers twiddle-table writes
    const float mean0 = (red[fid][0][0] + red[fid][1][0]) * (1.0f / FRAME_LEN);
    const float mean1 = (red[fid][0][1] + red[fid][1][1]) * (1.0f / FRAME_LEN);

    // ---- preemph + window straight into stage-1 registers ----
    float xr[8], xi[8];
    #pragma unroll
    for (int m = 0; m < 8; m++) {
        int i = lt + 64 * m;
        float v0 = 0.f, v1 = 0.f;
        if (i < FRAME_LEN) {
            float w  = window[i];
            float a0 = bR[i] - mean0;
            float q0 = ((i == 0) ? bR[0] : bR[i - 1]) - mean0;
            v0 = (a0 - PREEMPH * q0) * w;
            float a1 = bI[i] - mean1;
            float q1 = ((i == 0) ? bI[0] : bI[i - 1]) - mean1;
            v1 = (a1 - PREEMPH * q1) * w;
        }
        xr[m] = v0; xi[m] = v1;
    }

    // ---- stage 1: radix-8 over m (stride 64), twiddle W512^{u*j} ----
    fft8(xr, xi);
    #pragma unroll
    for (int j = 1; j < 8; j++) {
        int a = (lt * j) & 511;
        float c = twc[a], s = tws[a];
        float rr = xr[j] * c + xi[j] * s;
        xi[j] = xi[j] * c - xr[j] * s;
        xr[j] = rr;
    }

    // ---- exchange 1: z_j[u] -> thread (J=u'>>3, v=u'&7) gets z_J[v+8m] ----
    __syncthreads();   // raw-frame reads done; buffers reusable
    #pragma unroll
    for (int j = 0; j < 8; j++) {
        bR[72 * j + lt] = xr[j];
        bI[72 * j + lt] = xi[j];
    }
    __syncthreads();
    const int J = lt >> 3, v = lt & 7;
    #pragma unroll
    for (int m = 0; m < 8; m++) {
        xr[m] = bR[72 * J + v + 8 * m];
        xi[m] = bI[72 * J + v + 8 * m];
    }

    // ---- stage 2: radix-8 over m, twiddle W64^{v*i} = W512^{8vi} ----
    fft8(xr, xi);
    #pragma unroll
    for (int i = 1; i < 8; i++) {
        int a = 8 * v * i;
        float c = twc[a], s = tws[a];
        float rr = xr[i] * c + xi[i] * s;
        xi[i] = xi[i] * c - xr[i] * s;
        xr[i] = rr;
    }

    // ---- exchange 2: w_{J,i}[v] -> thread (J, I) gets all v ----
    __syncthreads();
    #pragma unroll
    for (int i = 0; i < 8; i++) {
        bR[72 * J + 8 * i + v] = xr[i];
        bI[72 * J + 8 * i + v] = xi[i];
    }
    __syncthreads();
    const int I = v;
    {
        const float4 r0 = *(const float4*)&bR[72 * J + 8 * I];
        const float4 r1 = *(const float4*)&bR[72 * J + 8 * I + 4];
        const float4 q0 = *(const float4*)&bI[72 * J + 8 * I];
        const float4 q1 = *(const float4*)&bI[72 * J + 8 * I + 4];
        xr[0]=r0.x; xr[1]=r0.y; xr[2]=r0.z; xr[3]=r0.w;
        xr[4]=r1.x; xr[5]=r1.y; xr[6]=r1.z; xr[7]=r1.w;
        xi[0]=q0.x; xi[1]=q0.y; xi[2]=q0.z; xi[3]=q0.w;
        xi[4]=q1.x; xi[5]=q1.y; xi[6]=q1.z; xi[7]=q1.w;
    }

    // ---- stage 3: radix-8 over v (no twiddle). Result: X[64s + 8I + J] ----
    fft8(xr, xi);

    // ---- store Z in natural order ----
    __syncthreads();
    #pragma unroll
    for (int s = 0; s < 8; s++) {
        bR[64 * s + 8 * I + J] = xr[s];
        bI[64 * s + 8 * I + J] = xi[s];
    }
    __syncthreads();

    // ---- conjugate-symmetry split + power (into regs, then smem) ----
    float p0[5], p1[5];
    int cnt = 0;
    for (int k = lt; k < NK; k += 64) {
        int n = (NFFT - k) & (NFFT - 1);
        float a = bR[k], bb = bI[k];
        float c = bR[n], d  = bI[n];
        float Xr = 0.5f * (a + c),  X2 = 0.5f * (bb - d);
        float Yr = 0.5f * (bb + d), Yi = 0.5f * (c - a);
        p0[cnt] = Xr * Xr + X2 * X2;
        p1[cnt] = Yr * Yr + Yi * Yi;
        cnt++;
    }
    __syncthreads();
    cnt = 0;
    for (int k = lt; k < NK; k += 64) {
        bR[k] = p0[cnt];
        bI[k] = p1[cnt];
        cnt++;
    }
    __syncthreads();

    // ---- sparse mel + log (160 outputs per pair over 64 threads) ----
    for (int idx = lt; idx < 2 * NMEL; idx += 64) {
        const int fr = (idx < NMEL) ? 0 : 1;
        const int m  = idx - fr * NMEL;
        const float* P = fr ? bI : bR;

        const float mel_lo = 1127.0f * logf(1.0f + 20.0f / 700.0f);
        const float mel_hi = 1127.0f * logf(1.0f + 8000.0f / 700.0f);
        const float delta  = (mel_hi - mel_lo) * (1.0f / (NMEL + 1));
        float left  = mel_lo + m * delta;
        float right = left + 2.0f * delta;
        float fl  = 700.0f * (expf(left  * (1.0f / 1127.0f)) - 1.0f);
        float fr_ = 700.0f * (expf(right * (1.0f / 1127.0f)) - 1.0f);
        int klo = max(0,   (int)floorf(fl  * (1.0f / 31.25f)) - 1);
        int khi = min(256, (int)ceilf (fr_ * (1.0f / 31.25f)) + 1);

        float acc = 0.f;
        for (int k = klo; k <= khi; k++)
            acc += P[k] * melf[(size_t)k * NMEL + m];

        if (valid)
            out[(size_t)(gm0 + fr) * NMEL + m] = logf(fmaxf(acc, EPS_F));
    }
}

// ================= CMN (vectorized) =================
__global__ __launch_bounds__(320)
void k_cmn_partial(const float* __restrict__ out)
{
    __shared__ float4 sm[320];
    const int ch = blockIdx.x, b = blockIdx.y;
    const int tid = threadIdx.x;
    const int lane = tid % 20;
    const int s    = tid / 20;
    const int f0   = ch * 120;
    const int fend = min(f0 + 120, NFRAMES);

    float4 acc = make_float4(0.f, 0.f, 0.f, 0.f);
    for (int f = f0 + s; f < fend; f += 16) {
        float4 v = *(const float4*)(out + ((size_t)b * NFRAMES + f) * NMEL + lane * 4);
        acc.x += v.x; acc.y += v.y; acc.z += v.z; acc.w += v.w;
    }
    sm[tid] = acc;
    __syncthreads();
    #pragma unroll
    for (int h = 8; h > 0; h >>= 1) {
        if (s < h) {
            float4 o_ = sm[tid + 20 * h];
            float4 m_ = sm[tid];
            m_.x += o_.x; m_.y += o_.y; m_.z += o_.z; m_.w += o_.w;
            sm[tid] = m_;
        }
        __syncthreads();
    }
    if (s == 0)
        *(float4*)(g_partial + ((size_t)b * NCHUNK + ch) * NMEL + lane * 4) = sm[lane];
}

__global__ void k_cmn_mean()
{
    int i = blockIdx.x * blockDim.x + threadIdx.x;
    if (i >= BATCH * NMEL) return;
    int b = i / NMEL, m = i % NMEL;
    float s = 0.f;
    #pragma unroll
    for (int c = 0; c < NCHUNK; c++)
        s += g_partial[(b * NCHUNK + c) * NMEL + m];
    g_mean[i] = s * (1.0f / NFRAMES);
}

__global__ void k_cmn_sub(float* __restrict__ out)
{
    size_t i = (size_t)blockIdx.x * blockDim.x + threadIdx.x;
    const size_t n4 = (size_t)M_TOTAL * (NMEL / 4);
    if (i >= n4) return;
    int m4 = (int)(i % (NMEL / 4));
    int b  = (int)(i / ((size_t)NFRAMES * (NMEL / 4)));
    float4 mu = *(const float4*)(g_mean + b * NMEL + m4 * 4);
    float4 v  = *(float4*)(out + i * 4);
    v.x -= mu.x; v.y -= mu.y; v.z -= mu.z; v.w -= mu.w;
    *(float4*)(out + i * 4) = v;
}

// ================= launch =================
extern "C" void kernel_launch(void* const* d_in, const int* in_sizes, int n_in,
                              void* d_out, int out_size)
{
    const float* wav    = (const float*)d_in[0];
    const float* window = (const float*)d_in[1];
    const float* melf   = (const float*)d_in[2];
    const float* dcos   = (const float*)d_in[3];
    const float* dsin   = (const float*)d_in[4];
    float* out = (float*)d_out;

    k_fused<<<dim3((NPAIRS + 1) / 2, BATCH), 128>>>(wav, window, melf, dcos, dsin, out);
    k_cmn_partial<<<dim3(NCHUNK, BATCH), 320>>>(out);
    k_cmn_mean<<<dim3((BATCH * NMEL + 255) / 256), 256>>>();
    {
        size_t n4 = (size_t)M_TOTAL * (NMEL / 4);
        k_cmn_sub<<<dim3((unsigned)((n4 + 255) / 256)), 256>>>(out);
    }
}